// round 7
// baseline (speedup 1.0000x reference)
#include <cuda_runtime.h>
#include <cuda_fp16.h>
#include <math.h>

#define BSZ 1024
#define T1  127
#define TP  128      // padded time dim for g_prex
#define HD  128
#define HE  128
#define ZD  512
#define GB  4        // batches per CTA
#define NCTA 256     // 256*4 = 1024

// global scratch (allowed: __device__ arrays)
__device__ __half g_prex[(size_t)BSZ * TP * HE];   // 33.5 MB, L2-resident
__device__ float  g_px2[BSZ * T1];
__device__ __half g_whh[HD * ZD];                  // Wh in fp16, 128 KB

static __device__ __forceinline__ float tanh_ap(float x){
    float r; asm("tanh.approx.f32 %0, %1;" : "=f"(r) : "f"(x)); return r;
}
static __device__ __forceinline__ float sig_ap(float x){
    return fmaf(0.5f, tanh_ap(0.5f * x), 0.5f);
}
static __device__ __forceinline__ unsigned tanh2_ap(unsigned x){
    unsigned r; asm("tanh.approx.f16x2 %0, %1;" : "=r"(r) : "r"(x)); return r;
}
static __device__ __forceinline__ unsigned h2u(__half2 h){
    union { __half2 h; unsigned u; } v; v.h = h; return v.u;
}
static __device__ __forceinline__ __half2 u2h(unsigned u){
    union { __half2 h; unsigned u; } v; v.u = u; return v.h;
}

// packed f32x2 helpers
#define FMA2(d,a,b,c)  asm("fma.rn.f32x2 %0, %1, %2, %3;" : "=l"(d) : "l"(a), "l"(b), "l"(c))
#define PACKB(d,x)     asm("mov.b64 %0, {%1,%1};" : "=l"(d) : "f"(x))
#define PACK2(d,x,y)   asm("mov.b64 %0, {%1,%2};" : "=l"(d) : "f"(x), "f"(y))
#define UNPACK2(x,y,d) asm("mov.b64 {%0,%1}, %2;" : "=f"(x), "=f"(y) : "l"(d))

__global__ void cvt_wh_kernel(const float* __restrict__ Wh)
{
    int i = blockIdx.x * 256 + threadIdx.x;
    g_whh[i] = __float2half(Wh[i]);
}

// ---------------------------------------------------------------------------
// Prepass: pre_x[b,t,e] = X[b,t,:]@W1_x + b1[e] (fp16, t padded to 128)
//          px2[b,t]     = X[b,t,:].Wfc[:128]
// ---------------------------------------------------------------------------
#define PRE_SMEM ((HD*HE + T1*HE) * 4)

__global__ void __launch_bounds__(256, 1)
prex_kernel(const float* __restrict__ X, const float* __restrict__ W1,
            const float* __restrict__ b1, const float* __restrict__ Wfc)
{
    extern __shared__ float sm[];
    float* sW = sm;            // 128*128
    float* sX = sm + HD * HE;  // 127*128
    int b = blockIdx.x;
    int tid = threadIdx.x, lane = tid & 31, wid = tid >> 5;
    const float* Xb = X + (size_t)b * T1 * HE;

    for (int i = tid; i < HD * HE; i += 256) sW[i] = W1[2 * HD * HE + i];
    for (int i = tid; i < T1 * HE; i += 256) sX[i] = Xb[i];
    __syncthreads();

    int e = tid & 127, th = tid >> 7;
    float b1e = b1[e];
    for (int t = th; t < T1; t += 2) {
        float acc = 0.f;
        const float* xr = sX + t * HE;
        #pragma unroll 8
        for (int k = 0; k < HE; k++) acc = fmaf(xr[k], sW[k * HE + e], acc);
        g_prex[((size_t)b * TP + t) * HE + e] = __float2half(acc + b1e);
    }
    if (tid < 128) g_prex[((size_t)b * TP + 127) * HE + tid] = __float2half(0.f);

    float4 wf = ((const float4*)Wfc)[lane];
    for (int t = wid; t < T1; t += 8) {
        float4 x = ((const float4*)(sX + t * HE))[lane];
        float p = x.x * wf.x + x.y * wf.y + x.z * wf.z + x.w * wf.w;
        #pragma unroll
        for (int m = 16; m; m >>= 1) p += __shfl_xor_sync(0xffffffffu, p, m);
        if (lane == 0) g_px2[b * T1 + t] = p;
    }
}

// ---------------------------------------------------------------------------
// Main persistent kernel: 256 CTAs x 4 batches x 256 threads (2 CTAs/SM)
// ---------------------------------------------------------------------------
// float-slot offsets
#define O_W1H  0                      // half2[128*128] interleaved (W1d,W1c) = 16384 slots
#define O_VA   16384                  // [2][4][128] = 1024
#define O_ZP   (O_VA + 1024)          // [2][4][512] = 4096
#define O_D    (O_ZP + 4096)          // 512  (transposed: sd_t[k*4+b])
#define O_C    (O_D + 512)            // 512
#define O_BETA (O_C + 512)            // 512  (beta[b*128+tp])
#define O_PX2  (O_BETA + 512)         // 512
#define O_YP   (O_PX2 + 512)          // 512
#define O_W2   (O_YP + 512)           // 128
#define O_WX   (O_W2 + 128)           // 512
#define O_BL   (O_WX + 512)           // 512
#define O_SSB  (O_BL + 512)           // 8
#define O_SQ   (O_SSB + 8)            // 4
#define MAIN_FLOATS (O_SQ + 4)
#define MAIN_SMEM (MAIN_FLOATS * 4)   // 100,928 B

struct Ctx {
    __half2* sW1h; float* sva; float* szp; float* sd; float* sc; float* sbeta;
    float* spx2; float* syp; float* sW2; float* sWx; float* sbl; float* ssb; float* sq;
};

// Phase B: attention scores + s = sum_t beta*px2 (one warp per (b,half))
static __device__ __forceinline__ void phaseB(const Ctx& cx, int b0, int b, int half_,
                                              int lane, bool last, float b2v)
{
    float4 a0 = ((const float4*)(cx.sva + 0*512 + b*128))[lane];
    float4 a1 = ((const float4*)(cx.sva + 1*512 + b*128))[lane];
    float4 vr = make_float4(a0.x+a1.x, a0.y+a1.y, a0.z+a1.z, a0.w+a1.w);
    float4 w2r = ((const float4*)cx.sW2)[lane];
    __half2 vr01 = __floats2half2_rn(vr.x, vr.y);
    __half2 vr23 = __floats2half2_rn(vr.z, vr.w);
    __half2 w01  = __floats2half2_rn(w2r.x, w2r.y);
    __half2 w23  = __floats2half2_rn(w2r.z, w2r.w);

    const uint2* pxb = ((const uint2*)(g_prex + (size_t)(b0 + b) * TP * HE)) + lane;
    const float* px2b = cx.spx2 + b * 128;
    float s_l = 0.f;
    int tp0 = half_ * 64;

    uint2 c0 = pxb[(tp0+0)*32], c1 = pxb[(tp0+1)*32];
    uint2 c2 = pxb[(tp0+2)*32], c3 = pxb[(tp0+3)*32];

    #pragma unroll 1
    for (int tc = 0; tc < 64; tc += 4) {
        int tp = tp0 + tc;
        int tn = (tc + 4 < 64) ? tp + 4 : tp;
        uint2 n0 = pxb[(tn+0)*32], n1 = pxb[(tn+1)*32];
        uint2 n2 = pxb[(tn+2)*32], n3 = pxb[(tn+3)*32];

        __half2 h0a = u2h(tanh2_ap(h2u(__hadd2(u2h(c0.x), vr01))));
        __half2 h0b = u2h(tanh2_ap(h2u(__hadd2(u2h(c0.y), vr23))));
        __half2 h1a = u2h(tanh2_ap(h2u(__hadd2(u2h(c1.x), vr01))));
        __half2 h1b = u2h(tanh2_ap(h2u(__hadd2(u2h(c1.y), vr23))));
        __half2 h2a = u2h(tanh2_ap(h2u(__hadd2(u2h(c2.x), vr01))));
        __half2 h2b = u2h(tanh2_ap(h2u(__hadd2(u2h(c2.y), vr23))));
        __half2 h3a = u2h(tanh2_ap(h2u(__hadd2(u2h(c3.x), vr01))));
        __half2 h3b = u2h(tanh2_ap(h2u(__hadd2(u2h(c3.y), vr23))));

        __half2 p0 = __hfma2(h0b, w23, __hmul2(h0a, w01));
        __half2 p1 = __hfma2(h1b, w23, __hmul2(h1a, w01));
        __half2 p2 = __hfma2(h2b, w23, __hmul2(h2a, w01));
        __half2 p3 = __hfma2(h3b, w23, __hmul2(h3a, w01));
        float2 q0 = __half22float2(p0);
        float2 q1 = __half22float2(p1);
        float2 q2 = __half22float2(p2);
        float2 q3 = __half22float2(p3);
        float pl0 = q0.x + q0.y, pl1 = q1.x + q1.y;
        float pl2 = q2.x + q2.y, pl3 = q3.x + q3.y;

        s_l = fmaf(pl0, px2b[tp+0], s_l);
        s_l = fmaf(pl1, px2b[tp+1], s_l);
        s_l = fmaf(pl2, px2b[tp+2], s_l);
        s_l = fmaf(pl3, px2b[tp+3], s_l);

        if (last) {
            float r0 = pl0, r1 = pl1, r2 = pl2, r3 = pl3;
            #pragma unroll
            for (int m = 16; m; m >>= 1) {
                r0 += __shfl_xor_sync(0xffffffffu, r0, m);
                r1 += __shfl_xor_sync(0xffffffffu, r1, m);
                r2 += __shfl_xor_sync(0xffffffffu, r2, m);
                r3 += __shfl_xor_sync(0xffffffffu, r3, m);
            }
            if (lane == 0) {
                cx.sbeta[b*128 + tp+0] = r0 + b2v;
                cx.sbeta[b*128 + tp+1] = r1 + b2v;
                cx.sbeta[b*128 + tp+2] = r2 + b2v;
                cx.sbeta[b*128 + tp+3] = r3 + b2v;
            }
        }
        c0 = n0; c1 = n1; c2 = n2; c3 = n3;
    }
    #pragma unroll
    for (int m = 16; m; m >>= 1) s_l += __shfl_xor_sync(0xffffffffu, s_l, m);
    if (lane == 0) cx.ssb[2*b + half_] = s_l;
}

// Phase C: z partials = d @ Wh  (f32x2, fp16 weights from L2)
static __device__ __forceinline__ void phaseC(const Ctx& cx, int tid)
{
    int jg = tid & 127, h = tid >> 7, kb = h * 64;
    const __half* whp = g_whh + (size_t)kb * ZD + jg * 4;
    unsigned long long a01[GB], a23[GB];
    #pragma unroll
    for (int b = 0; b < GB; b++) { a01[b] = 0ULL; a23[b] = 0ULL; }

    uint2 wc0 = *(const uint2*)(whp + 0*ZD);
    uint2 wc1 = *(const uint2*)(whp + 1*ZD);
    uint2 wc2 = *(const uint2*)(whp + 2*ZD);
    uint2 wc3 = *(const uint2*)(whp + 3*ZD);

    #pragma unroll 1
    for (int kk = 0; kk < 64; kk += 4) {
        int kn = (kk + 4 < 64) ? kk + 4 : kk;
        uint2 n0 = *(const uint2*)(whp + (size_t)(kn+0)*ZD);
        uint2 n1 = *(const uint2*)(whp + (size_t)(kn+1)*ZD);
        uint2 n2 = *(const uint2*)(whp + (size_t)(kn+2)*ZD);
        uint2 n3 = *(const uint2*)(whp + (size_t)(kn+3)*ZD);

        unsigned long long w01[4], w23[4];
        {
            float2 lo, hi;
            lo = __half22float2(u2h(wc0.x)); hi = __half22float2(u2h(wc0.y));
            PACK2(w01[0], lo.x, lo.y); PACK2(w23[0], hi.x, hi.y);
            lo = __half22float2(u2h(wc1.x)); hi = __half22float2(u2h(wc1.y));
            PACK2(w01[1], lo.x, lo.y); PACK2(w23[1], hi.x, hi.y);
            lo = __half22float2(u2h(wc2.x)); hi = __half22float2(u2h(wc2.y));
            PACK2(w01[2], lo.x, lo.y); PACK2(w23[2], hi.x, hi.y);
            lo = __half22float2(u2h(wc3.x)); hi = __half22float2(u2h(wc3.y));
            PACK2(w01[3], lo.x, lo.y); PACK2(w23[3], hi.x, hi.y);
        }
        #pragma unroll
        for (int r = 0; r < 4; r++) {
            float4 dv = *(const float4*)(cx.sd + (kb + kk + r) * 4);  // 4 batches at row k
            unsigned long long dd;
            PACKB(dd, dv.x); FMA2(a01[0], dd, w01[r], a01[0]); FMA2(a23[0], dd, w23[r], a23[0]);
            PACKB(dd, dv.y); FMA2(a01[1], dd, w01[r], a01[1]); FMA2(a23[1], dd, w23[r], a23[1]);
            PACKB(dd, dv.z); FMA2(a01[2], dd, w01[r], a01[2]); FMA2(a23[2], dd, w23[r], a23[2]);
            PACKB(dd, dv.w); FMA2(a01[3], dd, w01[r], a01[3]); FMA2(a23[3], dd, w23[r], a23[3]);
        }
        wc0 = n0; wc1 = n1; wc2 = n2; wc3 = n3;
    }
    #pragma unroll
    for (int b = 0; b < GB; b++) {
        float4 r;
        UNPACK2(r.x, r.y, a01[b]);
        UNPACK2(r.z, r.w, a23[b]);
        *(float4*)(cx.szp + h*2048 + b*512 + jg*4) = r;
    }
}

__global__ void __launch_bounds__(256, 2)
decoder_kernel(const float* __restrict__ X, const float* __restrict__ yprev,
               const float* __restrict__ W1, const float* __restrict__ W2,
               const float* __restrict__ b2, const float* __restrict__ Wfc,
               const float* __restrict__ bfc, const float* __restrict__ Wx,
               const float* __restrict__ Wh, const float* __restrict__ bl,
               const float* __restrict__ Wf, const float* __restrict__ bf,
               float* __restrict__ out)
{
    extern __shared__ float sm[];
    Ctx cx;
    cx.sW1h = (__half2*)(sm + O_W1H);
    cx.sva = sm + O_VA;  cx.szp = sm + O_ZP;
    cx.sd = sm + O_D;    cx.sc = sm + O_C;    cx.sbeta = sm + O_BETA;
    cx.spx2 = sm + O_PX2; cx.syp = sm + O_YP; cx.sW2 = sm + O_W2;
    cx.sWx = sm + O_WX;  cx.sbl = sm + O_BL;  cx.ssb = sm + O_SSB; cx.sq = sm + O_SQ;

    int tid = threadIdx.x, lane = tid & 31, wid = tid >> 5;
    int b0 = blockIdx.x * GB;

    // interleave (W1_d[k][e], W1_c[k][e]) into fp16 pairs
    for (int i = tid; i < HD * HE; i += 256)
        cx.sW1h[i] = __floats2half2_rn(W1[i], W1[HD * HE + i]);
    if (tid < 128) cx.sW2[tid] = W2[tid];
    for (int i = tid; i < 512; i += 256) { cx.sWx[i] = Wx[i]; cx.sbl[i] = bl[i]; }
    for (int i = tid; i < GB * 128; i += 256) {
        int b = i >> 7, tp = i & 127;
        cx.spx2[i] = (tp < T1) ? g_px2[(b0 + b) * T1 + tp] : 0.f;
        cx.syp[i]  = (tp < T1) ? yprev[(size_t)(b0 + b) * T1 + tp] : 0.f;
    }
    for (int i = tid; i < 512; i += 256) {     // transposed sd_t[k*4+b]
        int b = i & 3;
        float x00 = X[(size_t)(b0 + b) * T1 * HE];
        cx.sd[i] = x00; cx.sc[i] = x00;
    }
    float b2v  = b2[0];
    float bfcv = bfc[0];
    float wfcy = Wfc[HE];
    __syncthreads();
    if (wid < GB) {   // step-invariant q_b = sum_t px2[b,t]
        const float* p = cx.spx2 + wid * 128;
        float v = p[lane] + p[lane+32] + p[lane+64] + p[lane+96];
        #pragma unroll
        for (int m = 16; m; m >>= 1) v += __shfl_xor_sync(0xffffffffu, v, m);
        if (lane == 0) cx.sq[wid] = v;
    }

    for (int t = 0; t < T1; t++) {
        // ---- Phase A: v partials = d@W1_d + c@W1_c (fp16 weights, 2-way k-split) ----
        {
            int e = tid & 127, h = tid >> 7, kb = h * 64;
            float a0 = 0.f, a1 = 0.f, a2 = 0.f, a3 = 0.f;
            #pragma unroll 4
            for (int kk = 0; kk < 64; kk++) {
                int k = kb + kk;
                float2 w = __half22float2(cx.sW1h[k * 128 + e]);
                float4 dv = *(const float4*)(cx.sd + k * 4);
                float4 cv = *(const float4*)(cx.sc + k * 4);
                a0 = fmaf(dv.x, w.x, a0); a0 = fmaf(cv.x, w.y, a0);
                a1 = fmaf(dv.y, w.x, a1); a1 = fmaf(cv.y, w.y, a1);
                a2 = fmaf(dv.z, w.x, a2); a2 = fmaf(cv.z, w.y, a2);
                a3 = fmaf(dv.w, w.x, a3); a3 = fmaf(cv.w, w.y, a3);
            }
            float* va = cx.sva + h * 512 + e;
            va[0] = a0; va[128] = a1; va[256] = a2; va[384] = a3;
        }
        __syncthreads();

        // ---- Phase B (attention, f16x2) then C (d@Wh, f32x2) — all 8 warps ----
        {
            bool last = (t == T1 - 1);
            phaseB(cx, b0, wid >> 1, wid & 1, lane, last, b2v);
            phaseC(cx, tid);
        }
        __syncthreads();

        // ---- Phase D: assemble z, gates, update d/c (transposed) ----
        #pragma unroll
        for (int ii = 0; ii < 2; ii++) {
            int idx = tid + ii * 256;
            int b = idx & 3, k = idx >> 2;
            float s  = cx.ssb[2*b] + cx.ssb[2*b+1] + b2v * cx.sq[b];
            float yt = fmaf(cx.syp[b*128 + t], wfcy, s + bfcv);
            const float* zp = cx.szp + b * 512;
            float zi = zp[k]       + zp[2048 + k];
            float zf = zp[128 + k] + zp[2048 + 128 + k];
            float zg = zp[256 + k] + zp[2048 + 256 + k];
            float zo = zp[384 + k] + zp[2048 + 384 + k];
            zi = fmaf(yt, cx.sWx[k],       zi + cx.sbl[k]);
            zf = fmaf(yt, cx.sWx[128 + k], zf + cx.sbl[128 + k]);
            zg = fmaf(yt, cx.sWx[256 + k], zg + cx.sbl[256 + k]);
            zo = fmaf(yt, cx.sWx[384 + k], zo + cx.sbl[384 + k]);
            float cn = fmaf(sig_ap(zf), cx.sc[idx], sig_ap(zi) * tanh_ap(zg));
            cx.sc[idx] = cn;
            cx.sd[idx] = sig_ap(zo) * tanh_ap(cn);
        }
        __syncthreads();
    }

    // ---- Epilogue: ctx from final beta; out = d.Wf[:128] + ctx.Wf[128:] + bf ----
    if (wid < GB) {
        int b = wid;
        const float4* Xb = (const float4*)(X + (size_t)(b0 + b) * T1 * HE);
        float cxx = 0.f, cy = 0.f, cz = 0.f, cw = 0.f;
        for (int tp = 0; tp < T1; tp++) {
            float bb = cx.sbeta[b*128 + tp];
            float4 xv = Xb[tp*32 + lane];
            cxx = fmaf(bb, xv.x, cxx); cy = fmaf(bb, xv.y, cy);
            cz  = fmaf(bb, xv.z, cz);  cw = fmaf(bb, xv.w, cw);
        }
        float4 wfc2 = ((const float4*)(Wf + 128))[lane];
        float4 wfd  = ((const float4*)Wf)[lane];
        int e0 = lane * 4;
        float d0 = cx.sd[(e0+0)*4 + b], d1 = cx.sd[(e0+1)*4 + b];
        float d2 = cx.sd[(e0+2)*4 + b], d3 = cx.sd[(e0+3)*4 + b];
        float r = cxx*wfc2.x + cy*wfc2.y + cz*wfc2.z + cw*wfc2.w;
        r = fmaf(d0, wfd.x, r); r = fmaf(d1, wfd.y, r);
        r = fmaf(d2, wfd.z, r); r = fmaf(d3, wfd.w, r);
        #pragma unroll
        for (int m = 16; m; m >>= 1) r += __shfl_xor_sync(0xffffffffu, r, m);
        if (lane == 0) out[b0 + b] = r + bf[0];
    }
}

extern "C" void kernel_launch(void* const* d_in, const int* in_sizes, int n_in,
                              void* d_out, int out_size)
{
    const float* X    = (const float*)d_in[0];
    const float* yprev= (const float*)d_in[1];
    const float* W1   = (const float*)d_in[2];
    const float* b1   = (const float*)d_in[3];
    const float* W2   = (const float*)d_in[4];
    const float* b2   = (const float*)d_in[5];
    const float* Wfc  = (const float*)d_in[6];
    const float* bfc  = (const float*)d_in[7];
    const float* Wx   = (const float*)d_in[8];
    const float* Wh   = (const float*)d_in[9];
    const float* bl   = (const float*)d_in[10];
    const float* Wf   = (const float*)d_in[11];
    const float* bf   = (const float*)d_in[12];
    float* out = (float*)d_out;

    cudaFuncSetAttribute(prex_kernel, cudaFuncAttributeMaxDynamicSharedMemorySize, PRE_SMEM);
    cudaFuncSetAttribute(decoder_kernel, cudaFuncAttributeMaxDynamicSharedMemorySize, MAIN_SMEM);

    cvt_wh_kernel<<<HD * ZD / 256, 256>>>(Wh);
    prex_kernel<<<BSZ, 256, PRE_SMEM>>>(X, W1, b1, Wfc);
    decoder_kernel<<<NCTA, 256, MAIN_SMEM>>>(X, yprev, W1, W2, b2, Wfc, bfc,
                                             Wx, Wh, bl, Wf, bf, out);
}

// round 8
// speedup vs baseline: 1.1144x; 1.1144x over previous
#include <cuda_runtime.h>
#include <cuda_fp16.h>
#include <math.h>

#define BSZ 1024
#define T1  127
#define TP  128
#define HD  128
#define HE  128
#define ZD  512
#define GMAX 7
#define NCTA 147     // 147*7 = 1029 >= 1024
#define THREADS 1024

__device__ __half g_prex[(size_t)BSZ * TP * HE];   // 33.5 MB, L2-resident
__device__ float  g_px2[BSZ * T1];
__device__ __half g_whh[HD * ZD];                  // Wh fp16, 128 KB

static __device__ __forceinline__ float tanh_ap(float x){
    float r; asm("tanh.approx.f32 %0, %1;" : "=f"(r) : "f"(x)); return r;
}
static __device__ __forceinline__ float sig_ap(float x){
    return fmaf(0.5f, tanh_ap(0.5f * x), 0.5f);
}
static __device__ __forceinline__ unsigned tanh2_ap(unsigned x){
    unsigned r; asm("tanh.approx.f16x2 %0, %1;" : "=r"(r) : "r"(x)); return r;
}
static __device__ __forceinline__ unsigned h2u(__half2 h){
    union { __half2 h; unsigned u; } v; v.h = h; return v.u;
}
static __device__ __forceinline__ __half2 u2h(unsigned u){
    union { __half2 h; unsigned u; } v; v.u = u; return v.h;
}

#define FMA2(d,a,b,c)  asm("fma.rn.f32x2 %0, %1, %2, %3;" : "=l"(d) : "l"(a), "l"(b), "l"(c))
#define PACKB(d,x)     asm("mov.b64 %0, {%1,%1};" : "=l"(d) : "f"(x))
#define PACK2(d,x,y)   asm("mov.b64 %0, {%1,%2};" : "=l"(d) : "f"(x), "f"(y))
#define UNPACK2(x,y,d) asm("mov.b64 {%0,%1}, %2;" : "=f"(x), "=f"(y) : "l"(d))

// ---------------------------------------------------------------------------
// Prepass (also converts Wh -> fp16 in blocks 0..255)
// ---------------------------------------------------------------------------
#define PRE_SMEM ((HD*HE + T1*HE) * 4)

__global__ void __launch_bounds__(256, 1)
prex_kernel(const float* __restrict__ X, const float* __restrict__ W1,
            const float* __restrict__ b1, const float* __restrict__ Wfc,
            const float* __restrict__ Wh)
{
    extern __shared__ float sm[];
    float* sW = sm;            // 128*128
    float* sX = sm + HD * HE;  // 127*128
    int b = blockIdx.x;
    int tid = threadIdx.x, lane = tid & 31, wid = tid >> 5;
    const float* Xb = X + (size_t)b * T1 * HE;

    if (b < 256) g_whh[b * 256 + tid] = __float2half(Wh[b * 256 + tid]);

    for (int i = tid; i < HD * HE; i += 256) sW[i] = W1[2 * HD * HE + i];
    for (int i = tid; i < T1 * HE; i += 256) sX[i] = Xb[i];
    __syncthreads();

    int e = tid & 127, th = tid >> 7;
    float b1e = b1[e];
    for (int t = th; t < T1; t += 2) {
        float acc = 0.f;
        const float* xr = sX + t * HE;
        #pragma unroll 8
        for (int k = 0; k < HE; k++) acc = fmaf(xr[k], sW[k * HE + e], acc);
        g_prex[((size_t)b * TP + t) * HE + e] = __float2half(acc + b1e);
    }
    if (tid < 128) g_prex[((size_t)b * TP + 127) * HE + tid] = __float2half(0.f);

    float4 wf = ((const float4*)Wfc)[lane];
    for (int t = wid; t < T1; t += 8) {
        float4 x = ((const float4*)(sX + t * HE))[lane];
        float p = x.x * wf.x + x.y * wf.y + x.z * wf.z + x.w * wf.w;
        #pragma unroll
        for (int m = 16; m; m >>= 1) p += __shfl_xor_sync(0xffffffffu, p, m);
        if (lane == 0) g_px2[b * T1 + t] = p;
    }
}

// ---------------------------------------------------------------------------
// Main persistent kernel: 147 CTAs x 7 batches x 1024 threads (1 CTA/SM)
// ---------------------------------------------------------------------------
#define O_W1H  0                      // half2[128*128] = 16384 float slots (65.5KB)
#define O_VA   16384                  // [8][7][128] = 7168
#define O_ZP   (O_VA + 7168)          // [4][7][512] = 14336
#define O_D    (O_ZP + 14336)         // 896
#define O_C    (O_D + 896)            // 896
#define O_BETA (O_C + 896)            // 896
#define O_PX2  (O_BETA + 896)         // 896
#define O_YP   (O_PX2 + 896)          // 896
#define O_W2   (O_YP + 896)           // 128
#define O_WX   (O_W2 + 128)           // 512
#define O_BL   (O_WX + 512)           // 512
#define O_SSB  (O_BL + 512)           // 16
#define O_SQ   (O_SSB + 16)           // 8
#define MAIN_FLOATS (O_SQ + 8)
#define MAIN_SMEM (MAIN_FLOATS * 4)   // 174,176 B

struct Ctx {
    __half2* sW1h; float* sva; float* szp; float* sd; float* sc; float* sbeta;
    float* spx2; float* syp; float* sW2; float* sWx; float* sbl; float* ssb; float* sq;
};

// Phase B: one warp per (b, half); f16x2 attention + s accumulation
static __device__ __forceinline__ void phaseB(const Ctx& cx, int b0, int b, int half_,
                                              int lane, bool last, float b2v)
{
    float4 vr = make_float4(0.f, 0.f, 0.f, 0.f);
    #pragma unroll
    for (int h = 0; h < 8; h++) {
        float4 a = ((const float4*)(cx.sva + h*896 + b*128))[lane];
        vr.x += a.x; vr.y += a.y; vr.z += a.z; vr.w += a.w;
    }
    float4 w2r = ((const float4*)cx.sW2)[lane];
    __half2 vr01 = __floats2half2_rn(vr.x, vr.y);
    __half2 vr23 = __floats2half2_rn(vr.z, vr.w);
    __half2 w01  = __floats2half2_rn(w2r.x, w2r.y);
    __half2 w23  = __floats2half2_rn(w2r.z, w2r.w);

    const uint2* pxb = ((const uint2*)(g_prex + (size_t)(b0 + b) * TP * HE)) + lane;
    const float* px2b = cx.spx2 + b * 128;
    float s_l = 0.f;
    int tp0 = half_ * 64;

    uint2 c0 = pxb[(tp0+0)*32], c1 = pxb[(tp0+1)*32];
    uint2 c2 = pxb[(tp0+2)*32], c3 = pxb[(tp0+3)*32];

    #pragma unroll 1
    for (int tc = 0; tc < 64; tc += 4) {
        int tp = tp0 + tc;
        int tn = (tc + 4 < 64) ? tp + 4 : tp;
        uint2 n0 = pxb[(tn+0)*32], n1 = pxb[(tn+1)*32];
        uint2 n2 = pxb[(tn+2)*32], n3 = pxb[(tn+3)*32];

        __half2 h0a = u2h(tanh2_ap(h2u(__hadd2(u2h(c0.x), vr01))));
        __half2 h0b = u2h(tanh2_ap(h2u(__hadd2(u2h(c0.y), vr23))));
        __half2 h1a = u2h(tanh2_ap(h2u(__hadd2(u2h(c1.x), vr01))));
        __half2 h1b = u2h(tanh2_ap(h2u(__hadd2(u2h(c1.y), vr23))));
        __half2 h2a = u2h(tanh2_ap(h2u(__hadd2(u2h(c2.x), vr01))));
        __half2 h2b = u2h(tanh2_ap(h2u(__hadd2(u2h(c2.y), vr23))));
        __half2 h3a = u2h(tanh2_ap(h2u(__hadd2(u2h(c3.x), vr01))));
        __half2 h3b = u2h(tanh2_ap(h2u(__hadd2(u2h(c3.y), vr23))));

        __half2 p0 = __hfma2(h0b, w23, __hmul2(h0a, w01));
        __half2 p1 = __hfma2(h1b, w23, __hmul2(h1a, w01));
        __half2 p2 = __hfma2(h2b, w23, __hmul2(h2a, w01));
        __half2 p3 = __hfma2(h3b, w23, __hmul2(h3a, w01));
        float2 q0 = __half22float2(p0);
        float2 q1 = __half22float2(p1);
        float2 q2 = __half22float2(p2);
        float2 q3 = __half22float2(p3);
        float pl0 = q0.x + q0.y, pl1 = q1.x + q1.y;
        float pl2 = q2.x + q2.y, pl3 = q3.x + q3.y;

        s_l = fmaf(pl0, px2b[tp+0], s_l);
        s_l = fmaf(pl1, px2b[tp+1], s_l);
        s_l = fmaf(pl2, px2b[tp+2], s_l);
        s_l = fmaf(pl3, px2b[tp+3], s_l);

        if (last) {
            float r0 = pl0, r1 = pl1, r2 = pl2, r3 = pl3;
            #pragma unroll
            for (int m = 16; m; m >>= 1) {
                r0 += __shfl_xor_sync(0xffffffffu, r0, m);
                r1 += __shfl_xor_sync(0xffffffffu, r1, m);
                r2 += __shfl_xor_sync(0xffffffffu, r2, m);
                r3 += __shfl_xor_sync(0xffffffffu, r3, m);
            }
            if (lane == 0) {
                cx.sbeta[b*128 + tp+0] = r0 + b2v;
                cx.sbeta[b*128 + tp+1] = r1 + b2v;
                cx.sbeta[b*128 + tp+2] = r2 + b2v;
                cx.sbeta[b*128 + tp+3] = r3 + b2v;
            }
        }
        c0 = n0; c1 = n1; c2 = n2; c3 = n3;
    }
    #pragma unroll
    for (int m = 16; m; m >>= 1) s_l += __shfl_xor_sync(0xffffffffu, s_l, m);
    if (lane == 0) cx.ssb[2*b + half_] = s_l;
}

// Phase C: z partials = d @ Wh (warps 16-31; 512 threads; f32x2)
static __device__ __forceinline__ void phaseC(const Ctx& cx, int ctid)
{
    int jg = ctid & 127, h = ctid >> 7, kb = h * 32;
    const __half* whp = g_whh + (size_t)kb * ZD + jg * 4;
    unsigned long long a01[GMAX], a23[GMAX];
    #pragma unroll
    for (int b = 0; b < GMAX; b++) { a01[b] = 0ULL; a23[b] = 0ULL; }

    uint2 wc0 = *(const uint2*)(whp + 0*ZD);
    uint2 wc1 = *(const uint2*)(whp + 1*ZD);
    uint2 wc2 = *(const uint2*)(whp + 2*ZD);
    uint2 wc3 = *(const uint2*)(whp + 3*ZD);

    #pragma unroll 1
    for (int kk = 0; kk < 32; kk += 4) {
        int kn = (kk + 4 < 32) ? kk + 4 : kk;
        uint2 n0 = *(const uint2*)(whp + (size_t)(kn+0)*ZD);
        uint2 n1 = *(const uint2*)(whp + (size_t)(kn+1)*ZD);
        uint2 n2 = *(const uint2*)(whp + (size_t)(kn+2)*ZD);
        uint2 n3 = *(const uint2*)(whp + (size_t)(kn+3)*ZD);

        unsigned long long w01[4], w23[4];
        {
            float2 lo, hi;
            lo = __half22float2(u2h(wc0.x)); hi = __half22float2(u2h(wc0.y));
            PACK2(w01[0], lo.x, lo.y); PACK2(w23[0], hi.x, hi.y);
            lo = __half22float2(u2h(wc1.x)); hi = __half22float2(u2h(wc1.y));
            PACK2(w01[1], lo.x, lo.y); PACK2(w23[1], hi.x, hi.y);
            lo = __half22float2(u2h(wc2.x)); hi = __half22float2(u2h(wc2.y));
            PACK2(w01[2], lo.x, lo.y); PACK2(w23[2], hi.x, hi.y);
            lo = __half22float2(u2h(wc3.x)); hi = __half22float2(u2h(wc3.y));
            PACK2(w01[3], lo.x, lo.y); PACK2(w23[3], hi.x, hi.y);
        }
        #pragma unroll
        for (int b = 0; b < GMAX; b++) {
            float4 dv = *(const float4*)(cx.sd + b*128 + kb + kk);
            unsigned long long dd;
            PACKB(dd, dv.x); FMA2(a01[b], dd, w01[0], a01[b]); FMA2(a23[b], dd, w23[0], a23[b]);
            PACKB(dd, dv.y); FMA2(a01[b], dd, w01[1], a01[b]); FMA2(a23[b], dd, w23[1], a23[b]);
            PACKB(dd, dv.z); FMA2(a01[b], dd, w01[2], a01[b]); FMA2(a23[b], dd, w23[2], a23[b]);
            PACKB(dd, dv.w); FMA2(a01[b], dd, w01[3], a01[b]); FMA2(a23[b], dd, w23[3], a23[b]);
        }
        wc0 = n0; wc1 = n1; wc2 = n2; wc3 = n3;
    }
    #pragma unroll
    for (int b = 0; b < GMAX; b++) {
        float4 r;
        UNPACK2(r.x, r.y, a01[b]);
        UNPACK2(r.z, r.w, a23[b]);
        *(float4*)(cx.szp + h*3584 + b*512 + jg*4) = r;
    }
}

__global__ void __launch_bounds__(THREADS, 1)
decoder_kernel(const float* __restrict__ X, const float* __restrict__ yprev,
               const float* __restrict__ W1, const float* __restrict__ W2,
               const float* __restrict__ b2, const float* __restrict__ Wfc,
               const float* __restrict__ bfc, const float* __restrict__ Wx,
               const float* __restrict__ Wh, const float* __restrict__ bl,
               const float* __restrict__ Wf, const float* __restrict__ bf,
               float* __restrict__ out)
{
    extern __shared__ float sm[];
    Ctx cx;
    cx.sW1h = (__half2*)(sm + O_W1H);
    cx.sva = sm + O_VA;  cx.szp = sm + O_ZP;
    cx.sd = sm + O_D;    cx.sc = sm + O_C;    cx.sbeta = sm + O_BETA;
    cx.spx2 = sm + O_PX2; cx.syp = sm + O_YP; cx.sW2 = sm + O_W2;
    cx.sWx = sm + O_WX;  cx.sbl = sm + O_BL;  cx.ssb = sm + O_SSB; cx.sq = sm + O_SQ;

    int tid = threadIdx.x, lane = tid & 31, wid = tid >> 5;
    int b0 = blockIdx.x * GMAX;
    if (b0 >= BSZ) return;
    int nb = min(GMAX, BSZ - b0);

    for (int i = tid; i < HD * HE; i += THREADS)
        cx.sW1h[i] = __floats2half2_rn(W1[i], W1[HD * HE + i]);
    if (tid < 128) cx.sW2[tid] = W2[tid];
    if (tid < 512) { cx.sWx[tid] = Wx[tid]; cx.sbl[tid] = bl[tid]; }
    if (tid < 24)  { cx.ssb[tid & 15] = 0.f; if (tid < 8) cx.sq[tid] = 0.f; }
    if (tid < GMAX * 128) {
        int b = tid >> 7, tp = tid & 127;
        bool ok = (b < nb);
        cx.spx2[tid] = (ok && tp < T1) ? g_px2[(b0 + b) * T1 + tp] : 0.f;
        cx.syp[tid]  = (ok && tp < T1) ? yprev[(size_t)(b0 + b) * T1 + tp] : 0.f;
        float x00 = ok ? X[(size_t)(b0 + b) * T1 * HE] : 0.f;
        cx.sd[tid] = x00; cx.sc[tid] = x00;
    }
    float b2v  = b2[0];
    float bfcv = bfc[0];
    float wfcy = Wfc[HE];
    __syncthreads();
    if (wid < nb) {   // step-invariant q_b
        const float* p = cx.spx2 + wid * 128;
        float v = p[lane] + p[lane+32] + p[lane+64] + p[lane+96];
        #pragma unroll
        for (int m = 16; m; m >>= 1) v += __shfl_xor_sync(0xffffffffu, v, m);
        if (lane == 0) cx.sq[wid] = v;
    }

    for (int t = 0; t < T1; t++) {
        // ---- Phase A: v partials (fp16 W1, 8-way k-split, all 32 warps) ----
        {
            int e = tid & 127, h = tid >> 7, kb = h * 16;
            float acc[GMAX];
            #pragma unroll
            for (int b = 0; b < GMAX; b++) acc[b] = 0.f;
            #pragma unroll
            for (int kk = 0; kk < 16; kk += 4) {
                int k = kb + kk;
                float2 w0 = __half22float2(cx.sW1h[(k+0)*128 + e]);
                float2 w1 = __half22float2(cx.sW1h[(k+1)*128 + e]);
                float2 w2 = __half22float2(cx.sW1h[(k+2)*128 + e]);
                float2 w3 = __half22float2(cx.sW1h[(k+3)*128 + e]);
                #pragma unroll
                for (int b = 0; b < GMAX; b++) {
                    float4 dv = *(const float4*)(cx.sd + b*128 + k);
                    float4 cv = *(const float4*)(cx.sc + b*128 + k);
                    float a = acc[b];
                    a = fmaf(dv.x, w0.x, a); a = fmaf(cv.x, w0.y, a);
                    a = fmaf(dv.y, w1.x, a); a = fmaf(cv.y, w1.y, a);
                    a = fmaf(dv.z, w2.x, a); a = fmaf(cv.z, w2.y, a);
                    a = fmaf(dv.w, w3.x, a); a = fmaf(cv.w, w3.y, a);
                    acc[b] = a;
                }
            }
            #pragma unroll
            for (int b = 0; b < GMAX; b++) cx.sva[h*896 + b*128 + e] = acc[b];
        }
        __syncthreads();

        // ---- BC region: warps 0-13 attention, warps 16-31 d@Wh ----
        {
            bool last = (t == T1 - 1);
            if (wid < 14) {
                int b = wid >> 1;
                if (b < nb) phaseB(cx, b0, b, wid & 1, lane, last, b2v);
            } else if (wid >= 16) {
                phaseC(cx, tid - 512);
            }
        }
        __syncthreads();

        // ---- Phase D: assemble z, gates, update d/c ----
        if (tid < GMAX * 128) {
            int b = tid >> 7, k = tid & 127;
            float s  = cx.ssb[2*b] + cx.ssb[2*b+1] + b2v * cx.sq[b];
            float yt = fmaf(cx.syp[b*128 + t], wfcy, s + bfcv);
            const float* zp = cx.szp + b * 512;
            float zi = zp[k]     + zp[3584 + k]     + zp[7168 + k]     + zp[10752 + k];
            float zf = zp[128+k] + zp[3584 + 128+k] + zp[7168 + 128+k] + zp[10752 + 128+k];
            float zg = zp[256+k] + zp[3584 + 256+k] + zp[7168 + 256+k] + zp[10752 + 256+k];
            float zo = zp[384+k] + zp[3584 + 384+k] + zp[7168 + 384+k] + zp[10752 + 384+k];
            zi = fmaf(yt, cx.sWx[k],     zi + cx.sbl[k]);
            zf = fmaf(yt, cx.sWx[128+k], zf + cx.sbl[128+k]);
            zg = fmaf(yt, cx.sWx[256+k], zg + cx.sbl[256+k]);
            zo = fmaf(yt, cx.sWx[384+k], zo + cx.sbl[384+k]);
            float cn = fmaf(sig_ap(zf), cx.sc[tid], sig_ap(zi) * tanh_ap(zg));
            cx.sc[tid] = cn;
            cx.sd[tid] = sig_ap(zo) * tanh_ap(cn);
        }
        __syncthreads();
    }

    // ---- Epilogue ----
    if (wid < nb) {
        int b = wid;
        const float4* Xb = (const float4*)(X + (size_t)(b0 + b) * T1 * HE);
        float cxx = 0.f, cy = 0.f, cz = 0.f, cw = 0.f;
        for (int tp = 0; tp < T1; tp++) {
            float bb = cx.sbeta[b*128 + tp];
            float4 xv = Xb[tp*32 + lane];
            cxx = fmaf(bb, xv.x, cxx); cy = fmaf(bb, xv.y, cy);
            cz  = fmaf(bb, xv.z, cz);  cw = fmaf(bb, xv.w, cw);
        }
        float4 wfc2 = ((const float4*)(Wf + 128))[lane];
        float4 wfd  = ((const float4*)Wf)[lane];
        float4 dv   = ((const float4*)(cx.sd + b*128))[lane];
        float r = cxx*wfc2.x + cy*wfc2.y + cz*wfc2.z + cw*wfc2.w;
        r = fmaf(dv.x, wfd.x, r); r = fmaf(dv.y, wfd.y, r);
        r = fmaf(dv.z, wfd.z, r); r = fmaf(dv.w, wfd.w, r);
        #pragma unroll
        for (int m = 16; m; m >>= 1) r += __shfl_xor_sync(0xffffffffu, r, m);
        if (lane == 0) out[b0 + b] = r + bf[0];
    }
}

extern "C" void kernel_launch(void* const* d_in, const int* in_sizes, int n_in,
                              void* d_out, int out_size)
{
    const float* X    = (const float*)d_in[0];
    const float* yprev= (const float*)d_in[1];
    const float* W1   = (const float*)d_in[2];
    const float* b1   = (const float*)d_in[3];
    const float* W2   = (const float*)d_in[4];
    const float* b2   = (const float*)d_in[5];
    const float* Wfc  = (const float*)d_in[6];
    const float* bfc  = (const float*)d_in[7];
    const float* Wx   = (const float*)d_in[8];
    const float* Wh   = (const float*)d_in[9];
    const float* bl   = (const float*)d_in[10];
    const float* Wf   = (const float*)d_in[11];
    const float* bf   = (const float*)d_in[12];
    float* out = (float*)d_out;

    cudaFuncSetAttribute(prex_kernel, cudaFuncAttributeMaxDynamicSharedMemorySize, PRE_SMEM);
    cudaFuncSetAttribute(decoder_kernel, cudaFuncAttributeMaxDynamicSharedMemorySize, MAIN_SMEM);

    prex_kernel<<<BSZ, 256, PRE_SMEM>>>(X, W1, b1, Wfc, Wh);
    decoder_kernel<<<NCTA, THREADS, MAIN_SMEM>>>(X, yprev, W1, W2, b2, Wfc, bfc,
                                                 Wx, Wh, bl, Wf, bf, out);
}